// round 6
// baseline (speedup 1.0000x reference)
#include <cuda_runtime.h>
#include <cstdint>
#include <cstddef>

// Problem dims
#define VOCAB 32000
#define EMB   512
#define HID   512
#define BATCH 64
#define S_LEN 512

// ---------------------------------------------------------------------------
// Scratch (no allocation allowed -> __device__ global)
// ---------------------------------------------------------------------------
__device__ float g_xproj[(size_t)BATCH * S_LEN * HID]; // 64 MB scratch

// ---------------------------------------------------------------------------
// Packed f32x2 helpers (Blackwell)
// ---------------------------------------------------------------------------
__device__ __forceinline__ unsigned long long packdup(float v) {
    unsigned long long r;
    asm("mov.b64 %0, {%1, %1};" : "=l"(r) : "f"(v));
    return r;
}
__device__ __forceinline__ void ffma2(unsigned long long& acc,
                                      unsigned long long a,
                                      unsigned long long b) {
    asm("fma.rn.f32x2 %0, %1, %2, %0;" : "+l"(acc) : "l"(a), "l"(b));
}
__device__ __forceinline__ float2 unpack2(unsigned long long v) {
    float2 f;
    asm("mov.b64 {%0, %1}, %2;" : "=f"(f.x), "=f"(f.y) : "l"(v));
    return f;
}

// ---------------------------------------------------------------------------
// Kernel 1: x_proj = gather(emb, tok) @ W_ih^T + (b_ih + b_hh)
// BM=BN=128, BK=16, 256 threads, 8x8/thread, f32x2 FFMA, conflict-free maps.
// ---------------------------------------------------------------------------
__global__ void __launch_bounds__(256, 2)
xproj_kernel(const void* __restrict__ tok_raw,
             const float* __restrict__ emb,
             const float* __restrict__ W_ih,
             const float* __restrict__ b_ih,
             const float* __restrict__ b_hh)
{
    __shared__ float              As[16][128];      // A tile, [k][m]
    __shared__ unsigned long long Bsd[16][128];     // B tile, [k][n], dup {v,v}
    __shared__ int                toks[128];
    __shared__ int                s_tok64;

    const int tid = threadIdx.x;
    const int m0  = blockIdx.y * 128;
    const int n0  = blockIdx.x * 128;

    // int64 tokens (LE) => odd 32-bit words of the first 32 elements all zero.
    if (tid < 32) {
        int wv = ((const int*)tok_raw)[2 * tid + 1];
        unsigned nz = __ballot_sync(0xffffffffu, wv != 0);
        if (tid == 0) s_tok64 = (nz == 0u);
    }
    __syncthreads();

    if (tid < 128) {
        int m = m0 + tid;
        toks[tid] = s_tok64 ? (int)((const long long*)tok_raw)[m]
                            : ((const int*)tok_raw)[m];
    }
    __syncthreads();

    // Loaders: thread t loads row (t&127), k-seg ((t>>7)*8 .. +8)
    const int ldr_m   = tid & 127;
    const int ldr_seg = (tid >> 7) * 8;
    const float* arow_base = emb  + (size_t)toks[ldr_m] * EMB + ldr_seg;
    const float* brow_base = W_ih + (size_t)(n0 + ldr_m) * EMB + ldr_seg;

    const int ty = tid & 15;   // m sub-tile
    const int tx = tid >> 4;   // n sub-tile

    unsigned long long acc[32]; // acc[i2*8+j]: (m=ty*8+2*i2, m+1) x (n=n0+tx*8+j)
#pragma unroll
    for (int i = 0; i < 32; i++) acc[i] = 0ull;

    for (int kt = 0; kt < EMB / 16; kt++) {
        const int k0 = kt * 16;
        float4 av0 = *(const float4*)(arow_base + k0);
        float4 av1 = *(const float4*)(arow_base + k0 + 4);
        float4 bv0 = *(const float4*)(brow_base + k0);
        float4 bv1 = *(const float4*)(brow_base + k0 + 4);

        __syncthreads();   // previous tile fully consumed
        As[ldr_seg + 0][ldr_m] = av0.x;
        As[ldr_seg + 1][ldr_m] = av0.y;
        As[ldr_seg + 2][ldr_m] = av0.z;
        As[ldr_seg + 3][ldr_m] = av0.w;
        As[ldr_seg + 4][ldr_m] = av1.x;
        As[ldr_seg + 5][ldr_m] = av1.y;
        As[ldr_seg + 6][ldr_m] = av1.z;
        As[ldr_seg + 7][ldr_m] = av1.w;
        Bsd[ldr_seg + 0][ldr_m] = packdup(bv0.x);
        Bsd[ldr_seg + 1][ldr_m] = packdup(bv0.y);
        Bsd[ldr_seg + 2][ldr_m] = packdup(bv0.z);
        Bsd[ldr_seg + 3][ldr_m] = packdup(bv0.w);
        Bsd[ldr_seg + 4][ldr_m] = packdup(bv1.x);
        Bsd[ldr_seg + 5][ldr_m] = packdup(bv1.y);
        Bsd[ldr_seg + 6][ldr_m] = packdup(bv1.z);
        Bsd[ldr_seg + 7][ldr_m] = packdup(bv1.w);
        __syncthreads();

#pragma unroll
        for (int kk = 0; kk < 16; kk++) {
            ulonglong2 a01 = *(const ulonglong2*)&As[kk][ty * 8];
            ulonglong2 a23 = *(const ulonglong2*)&As[kk][ty * 8 + 4];
            unsigned long long ap[4] = { a01.x, a01.y, a23.x, a23.y };
            ulonglong2 b01 = *(const ulonglong2*)&Bsd[kk][tx * 8];
            ulonglong2 b23 = *(const ulonglong2*)&Bsd[kk][tx * 8 + 2];
            ulonglong2 b45 = *(const ulonglong2*)&Bsd[kk][tx * 8 + 4];
            ulonglong2 b67 = *(const ulonglong2*)&Bsd[kk][tx * 8 + 6];
            unsigned long long bd[8] = { b01.x, b01.y, b23.x, b23.y,
                                         b45.x, b45.y, b67.x, b67.y };
#pragma unroll
            for (int i2 = 0; i2 < 4; i2++)
#pragma unroll
                for (int j = 0; j < 8; j++)
                    ffma2(acc[i2 * 8 + j], ap[i2], bd[j]);
        }
    }

    // Epilogue: add (b_ih + b_hh), store
    float bias[8];
    {
        float4 x0 = *(const float4*)(b_ih + n0 + tx * 8);
        float4 x1 = *(const float4*)(b_ih + n0 + tx * 8 + 4);
        float4 y0 = *(const float4*)(b_hh + n0 + tx * 8);
        float4 y1 = *(const float4*)(b_hh + n0 + tx * 8 + 4);
        bias[0] = x0.x + y0.x;  bias[1] = x0.y + y0.y;
        bias[2] = x0.z + y0.z;  bias[3] = x0.w + y0.w;
        bias[4] = x1.x + y1.x;  bias[5] = x1.y + y1.y;
        bias[6] = x1.z + y1.z;  bias[7] = x1.w + y1.w;
    }
#pragma unroll
    for (int i2 = 0; i2 < 4; i2++) {
        float r0[8], r1[8];
#pragma unroll
        for (int j = 0; j < 8; j++) {
            float2 f = unpack2(acc[i2 * 8 + j]);
            r0[j] = f.x + bias[j];
            r1[j] = f.y + bias[j];
        }
        size_t mg = (size_t)(m0 + ty * 8 + i2 * 2);
        float* o0 = g_xproj + mg * HID + n0 + tx * 8;
        float* o1 = o0 + HID;
        *(float4*)(o0)     = make_float4(r0[0], r0[1], r0[2], r0[3]);
        *(float4*)(o0 + 4) = make_float4(r0[4], r0[5], r0[6], r0[7]);
        *(float4*)(o1)     = make_float4(r1[0], r1[1], r1[2], r1[3]);
        *(float4*)(o1 + 4) = make_float4(r1[4], r1[5], r1[6], r1[7]);
    }
}

// ---------------------------------------------------------------------------
// Kernel 2: recurrence. 16 clusters x 8 CTAs x 512 threads; cluster g owns
// batches [4g,4g+4). CTA rank j register-caches W_hh[:, 64j:64j+64).
// Per step: partials (f32x2) -> STS into per-destination stage -> sync ->
// 8 x cp.async.bulk (1KB each) to owner CTAs with remote-mbar complete_tx
// (8 transactions/owner/step instead of 1024 scalar st.async) -> owner
// try_waits its mbar (8192B) -> reduce + tanh -> double-buffered h_own.
// ---------------------------------------------------------------------------
#define CSZ 8
#define BG  4
#define KC  64
#define STEP_TX 8192              /* 8 bulk copies x 1024 B per owner */
#define DST_BYTES (BG * KC * 4 / CSZ * CSZ)  /* 1024 B per (src,dst) slab */

__global__ void __cluster_dims__(CSZ, 1, 1) __launch_bounds__(512, 1)
rnn_kernel(const float* __restrict__ W_hh, float* __restrict__ out)
{
    __shared__ float h_own[2][BG][KC];          // double-buffered h chunk (2 KB)
    __shared__ float recv[2][CSZ][BG * KC];     // [buf][src][hl*4 + b] (16 KB)
    __shared__ float stage[2][CSZ][BG * KC];    // [buf][dst][whl*4 + b] (16 KB)
    __shared__ unsigned long long mbar[2];

    const int tid = threadIdx.x;
    unsigned int rank;
    asm("mov.u32 %0, %%cluster_ctarank;" : "=r"(rank));
    const int cluster_id = blockIdx.x / CSZ;
    const int batch_base = cluster_id * BG;

    // Register-resident W_hh chunk: thread t holds W_hh[t][rank*64 .. +63]
    unsigned long long Wp[KC / 2];
    {
        const unsigned long long* wrow =
            (const unsigned long long*)(W_hh + (size_t)tid * HID + rank * KC);
#pragma unroll
        for (int i = 0; i < KC / 2; i++) Wp[i] = wrow[i];
    }

    if (tid < BG * KC) ((float*)h_own[0])[tid] = 0.0f;   // h0 = 0 (buffer 0)

    // mbarrier init + pre-post expects for the first two steps
    const unsigned int mbar0 = (unsigned int)__cvta_generic_to_shared(&mbar[0]);
    const unsigned int mbar1 = (unsigned int)__cvta_generic_to_shared(&mbar[1]);
    if (tid == 0) {
        asm volatile("mbarrier.init.shared.b64 [%0], 1;" :: "r"(mbar0) : "memory");
        asm volatile("mbarrier.init.shared.b64 [%0], 1;" :: "r"(mbar1) : "memory");
        asm volatile("mbarrier.arrive.expect_tx.shared.b64 _, [%0], %1;"
                     :: "r"(mbar0), "r"(STEP_TX) : "memory");
        asm volatile("mbarrier.arrive.expect_tx.shared.b64 _, [%0], %1;"
                     :: "r"(mbar1), "r"(STEP_TX) : "memory");
    }

    // Reduce-role (tid < 256): element (b = tid&3, hl = tid>>2)
    const int rb  = tid & 3;
    const int rhl = tid >> 2;
    const float* xp_base  = g_xproj + (size_t)(batch_base + rb) * S_LEN * HID + rank * KC + rhl;
    float*       out_base = out     + (size_t)(batch_base + rb) * S_LEN * HID + rank * KC + rhl;

    // Writer-role: thread t's output row h = t lives in CTA dst = t>>6
    const int dst = tid >> 6;
    const int whl = tid & 63;

    // Shared-address bases (32-bit shared window)
    const unsigned int stage_sa =
        (unsigned int)__cvta_generic_to_shared(&stage[0][0][0]);
    const unsigned int recv_rank_sa =
        (unsigned int)__cvta_generic_to_shared(&recv[0][rank][0]);
    // strides: buf stride = CSZ*1024 = 8192 B, slab stride = 1024 B

    __syncthreads();
    asm volatile("barrier.cluster.arrive.aligned;" ::: "memory");
    asm volatile("barrier.cluster.wait.aligned;"   ::: "memory");

    for (int s = 0; s < S_LEN; s++) {
        const int cur = s & 1;          // h buffer + comm buffer this step
        const int nxt = cur ^ 1;

        // Prefetch this step's xp (consumed after the mbar wait)
        float xpv = 0.0f;
        if (tid < 256) xpv = __ldg(xp_base + (size_t)s * HID);

        // Partials over local k-chunk, 4 batches (row h = tid)
        float p[BG];
#pragma unroll
        for (int b = 0; b < BG; b++) {
            unsigned long long a0 = 0ull, a1 = 0ull;
            const ulonglong2* hb = (const ulonglong2*)h_own[cur][b];
#pragma unroll
            for (int i = 0; i < KC / 4; i++) {
                ulonglong2 hv = hb[i];                 // broadcast LDS.128
                ffma2(a0, Wp[2 * i],     hv.x);
                ffma2(a1, Wp[2 * i + 1], hv.y);
            }
            unsigned long long asum;
            asm("add.rn.f32x2 %0, %1, %2;" : "=l"(asum) : "l"(a0), "l"(a1));
            float2 f = unpack2(asum);
            p[b] = f.x + f.y;
        }

        // Stage partials locally, grouped by destination CTA (16B per thread)
        *(float4*)&stage[cur][dst][whl * 4] = make_float4(p[0], p[1], p[2], p[3]);
        __syncthreads();

        // Lanes 0..7: one 1KB bulk copy per destination, remote-mbar complete_tx
        if (tid < CSZ) {
            const unsigned int d      = (unsigned)tid;
            const unsigned int src_sa = stage_sa + (unsigned)cur * 8192u + d * 1024u;
            const unsigned int dst_la = recv_rank_sa + (unsigned)cur * 8192u;
            const unsigned int mb_la  = cur ? mbar1 : mbar0;
            unsigned int dst_ra, mb_ra;
            asm("mapa.shared::cluster.u32 %0, %1, %2;" : "=r"(dst_ra) : "r"(dst_la), "r"(d));
            asm("mapa.shared::cluster.u32 %0, %1, %2;" : "=r"(mb_ra)  : "r"(mb_la),  "r"(d));
            asm volatile("fence.proxy.async.shared::cta;" ::: "memory");
            asm volatile(
                "cp.async.bulk.shared::cluster.shared::cta.mbarrier::complete_tx::bytes "
                "[%0], [%1], 1024, [%2];"
                :: "r"(dst_ra), "r"(src_sa), "r"(mb_ra) : "memory");
        }

        // Owner side: wait for all 8192 bytes (8 bulk copies)
        if (tid < 256) {
            const unsigned int mb = cur ? mbar1 : mbar0;
            const unsigned int parity = (unsigned)(s >> 1) & 1u;
            unsigned int done;
            asm volatile(
                "{\n\t.reg .pred p;\n\t"
                "mbarrier.try_wait.parity.acquire.cluster.shared::cta.b64 p, [%1], %2;\n\t"
                "selp.b32 %0, 1, 0, p;\n\t}"
                : "=r"(done) : "r"(mb), "r"(parity) : "memory");
            if (!done) {
                asm volatile(
                    "{\n\t.reg .pred P1;\n\t"
                    "WL_%=:\n\t"
                    "mbarrier.try_wait.parity.acquire.cluster.shared::cta.b64 P1, [%0], %1, 0x989680;\n\t"
                    "@P1 bra.uni WD_%=;\n\t"
                    "bra.uni WL_%=;\n\t"
                    "WD_%=:\n\t}"
                    :: "r"(mb), "r"(parity) : "memory");
            }

            // Reduce 8 partials + xp, tanh, write next h buffer + output
            float sum = xpv;
#pragma unroll
            for (int src = 0; src < CSZ; src++)
                sum += recv[cur][src][tid];
            float val = tanhf(sum);
            h_own[nxt][rb][rhl] = val;
            out_base[(size_t)s * HID] = val;

            // Re-arm this mbar for its next usage (step s+2)
            if (tid == 0) {
                asm volatile("mbarrier.arrive.expect_tx.shared.b64 _, [%0], %1;"
                             :: "r"(mb), "r"(STEP_TX) : "memory");
            }
        }
        __syncthreads();   // h_own[nxt] visible to all before next step
    }

    // hidden = h_T (final state lives in buffer S_LEN&1 = 0)
    if (tid < 256) {
        out[(size_t)BATCH * S_LEN * HID +
            (size_t)(batch_base + rb) * HID + rank * KC + rhl] = h_own[S_LEN & 1][rb][rhl];
    }

    asm volatile("barrier.cluster.arrive.aligned;" ::: "memory");
    asm volatile("barrier.cluster.wait.aligned;"   ::: "memory");
}

// ---------------------------------------------------------------------------
// Launch
// ---------------------------------------------------------------------------
extern "C" void kernel_launch(void* const* d_in, const int* in_sizes, int n_in,
                              void* d_out, int out_size)
{
    const void*  tok  = d_in[0];                 // (B,S) int32 or int64
    const float* emb  = (const float*)d_in[1];   // (V,E)
    const float* W_ih = (const float*)d_in[2];   // (H,E)
    const float* W_hh = (const float*)d_in[3];   // (H,H)
    const float* b_ih = (const float*)d_in[4];   // (H,)
    const float* b_hh = (const float*)d_in[5];   // (H,)
    float* out = (float*)d_out;                  // (B,S,H) outputs ++ (1,B,H) hidden

    dim3 grid_p1(HID / 128, (BATCH * S_LEN) / 128);   // (4, 256)
    xproj_kernel<<<grid_p1, 256>>>(tok, emb, W_ih, b_ih, b_hh);

    rnn_kernel<<<(BATCH / BG) * CSZ, 512>>>(W_hh, out);  // 128 CTAs = 16 clusters
}

// round 8
// speedup vs baseline: 1.0897x; 1.0897x over previous
#include <cuda_runtime.h>
#include <cstdint>
#include <cstddef>

// Problem dims
#define VOCAB 32000
#define EMB   512
#define HID   512
#define BATCH 64
#define S_LEN 512

// ---------------------------------------------------------------------------
// Scratch (no allocation allowed -> __device__ global)
// ---------------------------------------------------------------------------
__device__ float g_xproj[(size_t)BATCH * S_LEN * HID]; // 64 MB scratch

// ---------------------------------------------------------------------------
// Packed f32x2 helpers (Blackwell)
// ---------------------------------------------------------------------------
__device__ __forceinline__ unsigned long long packdup(float v) {
    unsigned long long r;
    asm("mov.b64 %0, {%1, %1};" : "=l"(r) : "f"(v));
    return r;
}
__device__ __forceinline__ void ffma2(unsigned long long& acc,
                                      unsigned long long a,
                                      unsigned long long b) {
    asm("fma.rn.f32x2 %0, %1, %2, %0;" : "+l"(acc) : "l"(a), "l"(b));
}
__device__ __forceinline__ float2 unpack2(unsigned long long v) {
    float2 f;
    asm("mov.b64 {%0, %1}, %2;" : "=f"(f.x), "=f"(f.y) : "l"(v));
    return f;
}

// ---------------------------------------------------------------------------
// Kernel 1: x_proj = gather(emb, tok) @ W_ih^T + (b_ih + b_hh)
// BM=BN=128, BK=16, 256 threads, 8x8/thread, f32x2 FFMA, conflict-free maps.
// ---------------------------------------------------------------------------
__global__ void __launch_bounds__(256, 2)
xproj_kernel(const void* __restrict__ tok_raw,
             const float* __restrict__ emb,
             const float* __restrict__ W_ih,
             const float* __restrict__ b_ih,
             const float* __restrict__ b_hh)
{
    __shared__ float              As[16][128];      // A tile, [k][m]
    __shared__ unsigned long long Bsd[16][128];     // B tile, [k][n], dup {v,v}
    __shared__ int                toks[128];
    __shared__ int                s_tok64;

    const int tid = threadIdx.x;
    const int m0  = blockIdx.y * 128;
    const int n0  = blockIdx.x * 128;

    // int64 tokens (LE) => odd 32-bit words of the first 32 elements all zero.
    if (tid < 32) {
        int wv = ((const int*)tok_raw)[2 * tid + 1];
        unsigned nz = __ballot_sync(0xffffffffu, wv != 0);
        if (tid == 0) s_tok64 = (nz == 0u);
    }
    __syncthreads();

    if (tid < 128) {
        int m = m0 + tid;
        toks[tid] = s_tok64 ? (int)((const long long*)tok_raw)[m]
                            : ((const int*)tok_raw)[m];
    }
    __syncthreads();

    // Loaders: thread t loads row (t&127), k-seg ((t>>7)*8 .. +8)
    const int ldr_m   = tid & 127;
    const int ldr_seg = (tid >> 7) * 8;
    const float* arow_base = emb  + (size_t)toks[ldr_m] * EMB + ldr_seg;
    const float* brow_base = W_ih + (size_t)(n0 + ldr_m) * EMB + ldr_seg;

    const int ty = tid & 15;   // m sub-tile
    const int tx = tid >> 4;   // n sub-tile

    unsigned long long acc[32]; // acc[i2*8+j]: (m=ty*8+2*i2, m+1) x (n=n0+tx*8+j)
#pragma unroll
    for (int i = 0; i < 32; i++) acc[i] = 0ull;

    for (int kt = 0; kt < EMB / 16; kt++) {
        const int k0 = kt * 16;
        float4 av0 = *(const float4*)(arow_base + k0);
        float4 av1 = *(const float4*)(arow_base + k0 + 4);
        float4 bv0 = *(const float4*)(brow_base + k0);
        float4 bv1 = *(const float4*)(brow_base + k0 + 4);

        __syncthreads();   // previous tile fully consumed
        As[ldr_seg + 0][ldr_m] = av0.x;
        As[ldr_seg + 1][ldr_m] = av0.y;
        As[ldr_seg + 2][ldr_m] = av0.z;
        As[ldr_seg + 3][ldr_m] = av0.w;
        As[ldr_seg + 4][ldr_m] = av1.x;
        As[ldr_seg + 5][ldr_m] = av1.y;
        As[ldr_seg + 6][ldr_m] = av1.z;
        As[ldr_seg + 7][ldr_m] = av1.w;
        Bsd[ldr_seg + 0][ldr_m] = packdup(bv0.x);
        Bsd[ldr_seg + 1][ldr_m] = packdup(bv0.y);
        Bsd[ldr_seg + 2][ldr_m] = packdup(bv0.z);
        Bsd[ldr_seg + 3][ldr_m] = packdup(bv0.w);
        Bsd[ldr_seg + 4][ldr_m] = packdup(bv1.x);
        Bsd[ldr_seg + 5][ldr_m] = packdup(bv1.y);
        Bsd[ldr_seg + 6][ldr_m] = packdup(bv1.z);
        Bsd[ldr_seg + 7][ldr_m] = packdup(bv1.w);
        __syncthreads();

#pragma unroll
        for (int kk = 0; kk < 16; kk++) {
            ulonglong2 a01 = *(const ulonglong2*)&As[kk][ty * 8];
            ulonglong2 a23 = *(const ulonglong2*)&As[kk][ty * 8 + 4];
            unsigned long long ap[4] = { a01.x, a01.y, a23.x, a23.y };
            ulonglong2 b01 = *(const ulonglong2*)&Bsd[kk][tx * 8];
            ulonglong2 b23 = *(const ulonglong2*)&Bsd[kk][tx * 8 + 2];
            ulonglong2 b45 = *(const ulonglong2*)&Bsd[kk][tx * 8 + 4];
            ulonglong2 b67 = *(const ulonglong2*)&Bsd[kk][tx * 8 + 6];
            unsigned long long bd[8] = { b01.x, b01.y, b23.x, b23.y,
                                         b45.x, b45.y, b67.x, b67.y };
#pragma unroll
            for (int i2 = 0; i2 < 4; i2++)
#pragma unroll
                for (int j = 0; j < 8; j++)
                    ffma2(acc[i2 * 8 + j], ap[i2], bd[j]);
        }
    }

    // Epilogue: add (b_ih + b_hh), store
    float bias[8];
    {
        float4 x0 = *(const float4*)(b_ih + n0 + tx * 8);
        float4 x1 = *(const float4*)(b_ih + n0 + tx * 8 + 4);
        float4 y0 = *(const float4*)(b_hh + n0 + tx * 8);
        float4 y1 = *(const float4*)(b_hh + n0 + tx * 8 + 4);
        bias[0] = x0.x + y0.x;  bias[1] = x0.y + y0.y;
        bias[2] = x0.z + y0.z;  bias[3] = x0.w + y0.w;
        bias[4] = x1.x + y1.x;  bias[5] = x1.y + y1.y;
        bias[6] = x1.z + y1.z;  bias[7] = x1.w + y1.w;
    }
#pragma unroll
    for (int i2 = 0; i2 < 4; i2++) {
        float r0[8], r1[8];
#pragma unroll
        for (int j = 0; j < 8; j++) {
            float2 f = unpack2(acc[i2 * 8 + j]);
            r0[j] = f.x + bias[j];
            r1[j] = f.y + bias[j];
        }
        size_t mg = (size_t)(m0 + ty * 8 + i2 * 2);
        float* o0 = g_xproj + mg * HID + n0 + tx * 8;
        float* o1 = o0 + HID;
        *(float4*)(o0)     = make_float4(r0[0], r0[1], r0[2], r0[3]);
        *(float4*)(o0 + 4) = make_float4(r0[4], r0[5], r0[6], r0[7]);
        *(float4*)(o1)     = make_float4(r1[0], r1[1], r1[2], r1[3]);
        *(float4*)(o1 + 4) = make_float4(r1[4], r1[5], r1[6], r1[7]);
    }
}

// ---------------------------------------------------------------------------
// Kernel 2: recurrence. 16 clusters x 8 CTAs x 512 threads; cluster g owns
// batches [4g,4g+4). CTA rank j register-caches W_hh[:, 64j:64j+64).
// Per step (warp-autonomous comm, ONE block barrier per step):
//   each warp: partials (f32x2) -> STS 512B warp slab -> syncwarp ->
//   lane0: cp.async.bulk 512B to its owner CTA (dst = warp>>1) with
//   remote-mbar complete_tx. Owner (tid<256) try_waits its mbar (8192B =
//   16 slabs), re-arms, reduces + tanh into double-buffered h_own, STG out.
//   One __syncthreads publishes h_own[nxt] to all warps.
// ---------------------------------------------------------------------------
#define CSZ 8
#define BG  4
#define KC  64
#define STEP_TX 8192              /* 16 slabs x 512 B per owner per step */

__global__ void __cluster_dims__(CSZ, 1, 1) __launch_bounds__(512, 1)
rnn_kernel(const float* __restrict__ W_hh, float* __restrict__ out)
{
    __shared__ float h_own[2][BG][KC];          // double-buffered h chunk (2 KB)
    __shared__ float recv[2][CSZ][BG * KC];     // [buf][src][whl*4 + b] (16 KB)
    __shared__ float stage[2][16][128];         // [buf][warp][lane*4 + b] (16 KB)
    __shared__ unsigned long long mbar[2];

    const int tid  = threadIdx.x;
    const int w    = tid >> 5;         // warp id 0..15
    const int lane = tid & 31;
    unsigned int rank;
    asm("mov.u32 %0, %%cluster_ctarank;" : "=r"(rank));
    const int cluster_id = blockIdx.x / CSZ;
    const int batch_base = cluster_id * BG;

    // Register-resident W_hh chunk: thread t holds W_hh[t][rank*64 .. +63]
    unsigned long long Wp[KC / 2];
    {
        const unsigned long long* wrow =
            (const unsigned long long*)(W_hh + (size_t)tid * HID + rank * KC);
#pragma unroll
        for (int i = 0; i < KC / 2; i++) Wp[i] = wrow[i];
    }

    if (tid < BG * KC) ((float*)h_own[0])[tid] = 0.0f;   // h0 = 0 (buffer 0)

    // mbarrier init + pre-post expects for the first two steps
    const unsigned int mbar0 = (unsigned int)__cvta_generic_to_shared(&mbar[0]);
    const unsigned int mbar1 = (unsigned int)__cvta_generic_to_shared(&mbar[1]);
    if (tid == 0) {
        asm volatile("mbarrier.init.shared.b64 [%0], 1;" :: "r"(mbar0) : "memory");
        asm volatile("mbarrier.init.shared.b64 [%0], 1;" :: "r"(mbar1) : "memory");
        asm volatile("mbarrier.arrive.expect_tx.shared.b64 _, [%0], %1;"
                     :: "r"(mbar0), "r"(STEP_TX) : "memory");
        asm volatile("mbarrier.arrive.expect_tx.shared.b64 _, [%0], %1;"
                     :: "r"(mbar1), "r"(STEP_TX) : "memory");
    }

    // Reduce-role (tid < 256): element (b = tid&3, whl = tid>>2)
    const int rb  = tid & 3;
    const int rhl = tid >> 2;
    const float* xp_base  = g_xproj + (size_t)(batch_base + rb) * S_LEN * HID + rank * KC + rhl;
    float*       out_base = out     + (size_t)(batch_base + rb) * S_LEN * HID + rank * KC + rhl;

    // Writer-role: warp w's 32 rows all live in CTA dstw = w>>1, half hh = w&1
    const unsigned int dstw = (unsigned)(w >> 1);
    const unsigned int hh   = (unsigned)(w & 1);

    // Precompute per-warp remote addresses for both buffers (lane 0 uses them)
    const unsigned int stage_sa =
        (unsigned int)__cvta_generic_to_shared(&stage[0][0][0]);
    const unsigned int recv_rank_sa =
        (unsigned int)__cvta_generic_to_shared(&recv[0][rank][0]);
    unsigned int dst_ra[2], mb_ra[2];
#pragma unroll
    for (int b = 0; b < 2; b++) {
        unsigned int dst_la = recv_rank_sa + (unsigned)b * 8192u + hh * 512u;
        unsigned int mb_la  = b ? mbar1 : mbar0;
        asm("mapa.shared::cluster.u32 %0, %1, %2;" : "=r"(dst_ra[b]) : "r"(dst_la), "r"(dstw));
        asm("mapa.shared::cluster.u32 %0, %1, %2;" : "=r"(mb_ra[b])  : "r"(mb_la),  "r"(dstw));
    }

    __syncthreads();
    asm volatile("barrier.cluster.arrive.aligned;" ::: "memory");
    asm volatile("barrier.cluster.wait.aligned;"   ::: "memory");

    // xp prefetch pipeline (2-step depth)
    float xpv_cur = (tid < 256) ? __ldg(xp_base) : 0.0f;

    for (int s = 0; s < S_LEN; s++) {
        const int cur = s & 1;          // h buffer + comm buffer this step
        const int nxt = cur ^ 1;

        // Prefetch next step's xp early (hides any L2/DRAM miss fully)
        float xpv_next = 0.0f;
        if (tid < 256 && s + 1 < S_LEN)
            xpv_next = __ldg(xp_base + (size_t)(s + 1) * HID);

        // Partials over local k-chunk, 4 batches (row h = tid)
        float p[BG];
#pragma unroll
        for (int b = 0; b < BG; b++) {
            unsigned long long a0 = 0ull, a1 = 0ull;
            const ulonglong2* hb = (const ulonglong2*)h_own[cur][b];
#pragma unroll
            for (int i = 0; i < KC / 4; i++) {
                ulonglong2 hv = hb[i];                 // broadcast LDS.128
                ffma2(a0, Wp[2 * i],     hv.x);
                ffma2(a1, Wp[2 * i + 1], hv.y);
            }
            unsigned long long asum;
            asm("add.rn.f32x2 %0, %1, %2;" : "=l"(asum) : "l"(a0), "l"(a1));
            float2 f = unpack2(asum);
            p[b] = f.x + f.y;
        }

        // Warp-autonomous send: stage 512B slab, syncwarp, lane0 bulk-copies it
        *(float4*)&stage[cur][w][lane * 4] = make_float4(p[0], p[1], p[2], p[3]);
        __syncwarp();
        if (lane == 0) {
            const unsigned int src_sa = stage_sa + (unsigned)cur * 8192u + (unsigned)w * 512u;
            asm volatile("fence.proxy.async.shared::cta;" ::: "memory");
            asm volatile(
                "cp.async.bulk.shared::cluster.shared::cta.mbarrier::complete_tx::bytes "
                "[%0], [%1], 512, [%2];"
                :: "r"(dst_ra[cur]), "r"(src_sa), "r"(mb_ra[cur]) : "memory");
        }

        // Owner side: wait for all 8192 bytes (16 slabs), re-arm, reduce
        if (tid < 256) {
            const unsigned int mb = cur ? mbar1 : mbar0;
            const unsigned int parity = (unsigned)(s >> 1) & 1u;
            unsigned int done;
            asm volatile(
                "{\n\t.reg .pred p;\n\t"
                "mbarrier.try_wait.parity.acquire.cluster.shared::cta.b64 p, [%1], %2;\n\t"
                "selp.b32 %0, 1, 0, p;\n\t}"
                : "=r"(done) : "r"(mb), "r"(parity) : "memory");
            if (!done) {
                asm volatile(
                    "{\n\t.reg .pred P1;\n\t"
                    "WL_%=:\n\t"
                    "mbarrier.try_wait.parity.acquire.cluster.shared::cta.b64 P1, [%0], %1, 0x989680;\n\t"
                    "@P1 bra.uni WD_%=;\n\t"
                    "bra.uni WL_%=;\n\t"
                    "WD_%=:\n\t}"
                    :: "r"(mb), "r"(parity) : "memory");
            }

            // Re-arm this mbar for its next usage (step s+2) right away
            if (tid == 0) {
                asm volatile("mbarrier.arrive.expect_tx.shared.b64 _, [%0], %1;"
                             :: "r"(mb), "r"(STEP_TX) : "memory");
            }

            // Reduce 8 partials + xp, tanh, write next h buffer + output
            float sum = xpv_cur;
#pragma unroll
            for (int src = 0; src < CSZ; src++)
                sum += recv[cur][src][tid];
            float val = tanhf(sum);
            h_own[nxt][rb][rhl] = val;
            out_base[(size_t)s * HID] = val;
        }
        xpv_cur = xpv_next;
        __syncthreads();   // h_own[nxt] visible to all before next step
    }

    // hidden = h_T (final state lives in buffer S_LEN&1 = 0)
    if (tid < 256) {
        out[(size_t)BATCH * S_LEN * HID +
            (size_t)(batch_base + rb) * HID + rank * KC + rhl] = h_own[S_LEN & 1][rb][rhl];
    }

    asm volatile("barrier.cluster.arrive.aligned;" ::: "memory");
    asm volatile("barrier.cluster.wait.aligned;"   ::: "memory");
}

// ---------------------------------------------------------------------------
// Launch
// ---------------------------------------------------------------------------
extern "C" void kernel_launch(void* const* d_in, const int* in_sizes, int n_in,
                              void* d_out, int out_size)
{
    const void*  tok  = d_in[0];                 // (B,S) int32 or int64
    const float* emb  = (const float*)d_in[1];   // (V,E)
    const float* W_ih = (const float*)d_in[2];   // (H,E)
    const float* W_hh = (const float*)d_in[3];   // (H,H)
    const float* b_ih = (const float*)d_in[4];   // (H,)
    const float* b_hh = (const float*)d_in[5];   // (H,)
    float* out = (float*)d_out;                  // (B,S,H) outputs ++ (1,B,H) hidden

    dim3 grid_p1(HID / 128, (BATCH * S_LEN) / 128);   // (4, 256)
    xproj_kernel<<<grid_p1, 256>>>(tok, emb, W_ih, b_ih, b_hh);

    rnn_kernel<<<(BATCH / BG) * CSZ, 512>>>(W_hh, out);  // 128 CTAs = 16 clusters
}